// round 3
// baseline (speedup 1.0000x reference)
#include <cuda_runtime.h>

// out[b, i, f] = x[b, i] * W[i, f] + bias[i, f]
// BS=16384, DEMO_DIM=32, FEAT_DIM=256  -> out = 134,217,728 fp32 (512 MiB)
// Pure HBM-write-bound: 1 float4 store per thread, fully coalesced.

#define BS       16384
#define DEMO_DIM 32
#define FEAT_DIM 256
#define F4       (FEAT_DIM / 4)            // 64 float4 per (b,i) row
#define TOTAL4   (BS * DEMO_DIM * F4)      // 33,554,432 float4 stores

__global__ __launch_bounds__(256) void demo_proj_kernel(
    const float* __restrict__ x,      // [BS, DEMO_DIM]
    const float4* __restrict__ W4,    // [DEMO_DIM, F4]
    const float4* __restrict__ B4,    // [DEMO_DIM, F4]
    float4* __restrict__ out4)        // [BS, DEMO_DIM, F4]
{
    int idx = blockIdx.x * blockDim.x + threadIdx.x;
    if (idx >= TOTAL4) return;

    int f4 = idx & (F4 - 1);          // 0..63
    int i  = (idx >> 6) & (DEMO_DIM - 1);
    int bb = idx >> 11;               // batch index

    float  xv = __ldg(&x[bb * DEMO_DIM + i]);   // 64 lanes broadcast same value
    float4 w  = __ldg(&W4[i * F4 + f4]);        // L1-resident after first wave
    float4 bv = __ldg(&B4[i * F4 + f4]);

    float4 o;
    o.x = fmaf(xv, w.x, bv.x);
    o.y = fmaf(xv, w.y, bv.y);
    o.z = fmaf(xv, w.z, bv.z);
    o.w = fmaf(xv, w.w, bv.w);

    out4[idx] = o;
}

extern "C" void kernel_launch(void* const* d_in, const int* in_sizes, int n_in,
                              void* d_out, int out_size)
{
    const float*  x  = (const float*)d_in[0];
    const float4* W4 = (const float4*)d_in[1];
    const float4* B4 = (const float4*)d_in[2];
    float4* out4 = (float4*)d_out;

    const int threads = 256;
    const int blocks  = TOTAL4 / threads;   // 131072 blocks, exact division
    demo_proj_kernel<<<blocks, threads>>>(x, W4, B4, out4);
}

// round 6
// speedup vs baseline: 1.5472x; 1.5472x over previous
#include <cuda_runtime.h>

// out[b, i, f] = x[b, i] * W[i, f] + bias[i, f]
// BS=16384, DEMO_DIM=32, FEAT_DIM=256 -> 512 MiB fp32 out. Pure HBM-store-bound.
//
// Round-3 changes vs round-0:
//  - 8 float4 stores per thread, iterating over BATCHES with fixed (i, f4):
//    W/b loaded ONCE per thread into registers (8x reuse), only x re-loaded
//    (L1 broadcast hit). Cuts L1 load traffic ~4x.
//  - Grid 131072 -> 16384 CTAs: ~110 waves -> ~14 waves (kills wave-transition
//    + tail overhead per B300 T_chip model).
//  - __stcs streaming stores: output is write-once, evict-first in L2.

#define BS        16384
#define DEMO_DIM  32
#define FEAT_DIM  256
#define F4        (FEAT_DIM / 4)                 // 64 float4 per (b,i)
#define ROW4      (DEMO_DIM * F4)                // 2048 float4 per batch
#define BPT       8                              // batches per thread
#define THREADS   256
#define OFF_CHUNKS (ROW4 / THREADS)              // 8 chunks of 256 float4 per row
#define NBLOCKS   ((BS / BPT) * OFF_CHUNKS)      // 2048 * 8 = 16384 blocks

__global__ __launch_bounds__(THREADS) void demo_proj_kernel(
    const float*  __restrict__ x,     // [BS, DEMO_DIM]
    const float4* __restrict__ W4,    // [DEMO_DIM, F4]
    const float4* __restrict__ B4,    // [DEMO_DIM, F4]
    float4*       __restrict__ out4)  // [BS, DEMO_DIM, F4]
{
    // Decompose block id: low 3 bits pick which 256-float4 chunk of the
    // 2048-float4 row, high bits pick the batch group of BPT batches.
    int off_chunk = blockIdx.x & (OFF_CHUNKS - 1);
    int bgroup    = blockIdx.x >> 3;

    int off = off_chunk * THREADS + threadIdx.x;   // 0..2047, fixed per thread
    int i   = off >> 6;                            // demo index, fixed
    int f4  = off & (F4 - 1);                      // feature chunk, fixed

    // Load the per-thread W/b ONCE; reused for all BPT batches.
    float4 w  = __ldg(&W4[i * F4 + f4]);
    float4 bv = __ldg(&B4[i * F4 + f4]);

    int bb0 = bgroup * BPT;
    const float* xrow = x + bb0 * DEMO_DIM + i;
    float4* dst = out4 + (long long)bb0 * ROW4 + off;

#pragma unroll
    for (int k = 0; k < BPT; k++) {
        float xv = __ldg(xrow + k * DEMO_DIM);     // 64 lanes broadcast, L1 hit
        float4 o;
        o.x = fmaf(xv, w.x, bv.x);
        o.y = fmaf(xv, w.y, bv.y);
        o.z = fmaf(xv, w.z, bv.z);
        o.w = fmaf(xv, w.w, bv.w);
        __stcs(dst + (long long)k * ROW4, o);      // streaming store, warp-coalesced
    }
}

extern "C" void kernel_launch(void* const* d_in, const int* in_sizes, int n_in,
                              void* d_out, int out_size)
{
    const float*  x  = (const float*)d_in[0];
    const float4* W4 = (const float4*)d_in[1];
    const float4* B4 = (const float4*)d_in[2];
    float4* out4 = (float4*)d_out;

    demo_proj_kernel<<<NBLOCKS, THREADS>>>(x, W4, B4, out4);
}